// round 11
// baseline (speedup 1.0000x reference)
#include <cuda_runtime.h>
#include <cuda_bf16.h>
#include <math.h>

// Problem constants (fixed by the reference)
#define BN    8192
#define CN    2048
#define LN    6
#define HALF  4096
#define MN    (BN + LN)          // 8198
#define XOUT_ELEMS ((size_t)MN * CN)
#define ADJ_OFF    XOUT_ELEMS

#define G       4                // rows staged per group (pass)
#define NGRP    16               // groups per pass block (64 rows/block)
#define NPASS   128              // pass blocks
#define NADJ    168              // adj blocks
#define NBLKS   (NPASS + NADJ)   // 296 total

// ---- scratch (no allocations; zero-initialized at module load, and the
//      finisher block re-zeroes after每 use so graph replays see zeros) ----
__device__ float    g_U[LN * CN];
__device__ float    g_denom[LN];
__device__ float    g_cnt[LN];
__device__ unsigned g_done;      // pass-block completion ticket

// ---------------------------------------------------------------------------
// Fused kernel.
//   blocks [0,128):   pass — group-staged score + copy + weighted accumulate
//                     (identical logic to the validated R8 pass_kernel);
//                     the LAST pass block to flush computes the tail rows and
//                     resets the scratch for the next replay.
//   blocks [128,296): adj — frozen constant segmented fill, rows strided.
// ---------------------------------------------------------------------------
__global__ void __launch_bounds__(256) fused_kernel(
    const float* __restrict__ x, const int* __restrict__ cams,
    const float* __restrict__ att_w, const float* __restrict__ att_b,
    const float* __restrict__ rmean, float* __restrict__ out)
{
    __shared__ float sx[G][CN];      // 32 KB staged rows (pass blocks only)
    __shared__ float sscore[G];
    __shared__ int   scam[G];
    __shared__ float sden[LN];
    __shared__ float scnt[LN];
    __shared__ int   sIsLast;

    const int t = threadIdx.x;

    if (blockIdx.x < NPASS) {
        // ================= PASS =================
        const int w = t >> 5, lane = t & 31;
        if (t < LN) { sden[t] = 0.0f; scnt[t] = 0.0f; }

        float acc[LN][8];
#pragma unroll
        for (int l = 0; l < LN; ++l)
#pragma unroll
            for (int k = 0; k < 8; ++k) acc[l][k] = 0.0f;

        const int r0 = blockIdx.x * (G * NGRP);      // 64 rows per block
        const float4* __restrict__ x4 = (const float4*)x;
        const float4* __restrict__ w4 = (const float4*)att_w;
        float4* __restrict__ o4 = (float4*)out;

        float4 buf[8];
#pragma unroll
        for (int m = 0; m < 8; ++m) {
            const int f = t + 256 * m;
            buf[m] = x4[(size_t)(r0 + (f >> 9)) * 512 + (f & 511)];
        }

        for (int g = 0; g < NGRP; ++g) {
            const int rows = r0 + G * g;

            __syncthreads();

            // stage to smem + fused copy to out
#pragma unroll
            for (int m = 0; m < 8; ++m) {
                const int f = t + 256 * m;
                const int rig = f >> 9, c4 = f & 511;
                *(float4*)&sx[rig][4 * c4] = buf[m];
                o4[(size_t)(rows + rig) * 512 + c4] = buf[m];
            }
            if (t < G) scam[t] = __ldg(&cams[rows + t]);
            __syncthreads();

            // score: warp w scores row w
            if (w < G) {
                const int cam = scam[w];
                float s = 0.0f;
#pragma unroll
                for (int k = 0; k < 16; ++k) {
                    const int c4 = lane + 32 * k;
                    const float4 xv = *(const float4*)&sx[w][4 * c4];
                    const float4 wv = __ldg(&w4[(size_t)cam * 512 + c4]);
                    s += xv.x * wv.x + xv.y * wv.y + xv.z * wv.z + xv.w * wv.w;
                }
#pragma unroll
                for (int o = 16; o > 0; o >>= 1) s += __shfl_down_sync(0xffffffffu, s, o);
                if (lane == 0) {
                    s += __ldg(&att_b[cam]);
                    sscore[w] = s;
                    atomicAdd(&sden[cam], s);
                    atomicAdd(&scnt[cam], 1.0f);
                }
            }
            __syncthreads();

            // prefetch next group before the accumulate
            if (g + 1 < NGRP) {
#pragma unroll
                for (int m = 0; m < 8; ++m) {
                    const int f = t + 256 * m;
                    buf[m] = x4[(size_t)(rows + G + (f >> 9)) * 512 + (f & 511)];
                }
            }

            // accumulate: 4 rows x 8 owned cols
#pragma unroll
            for (int r = 0; r < G; ++r) {
                const float s = sscore[r];
                const int cam = scam[r];
                const float4 xa = *(const float4*)&sx[r][4 * t];
                const float4 xb = *(const float4*)&sx[r][1024 + 4 * t];
#pragma unroll
                for (int l = 0; l < LN; ++l) {
                    const float sl = (cam == l) ? s : 0.0f;
                    acc[l][0] += sl * xa.x;  acc[l][1] += sl * xa.y;
                    acc[l][2] += sl * xa.z;  acc[l][3] += sl * xa.w;
                    acc[l][4] += sl * xb.x;  acc[l][5] += sl * xb.y;
                    acc[l][6] += sl * xb.z;  acc[l][7] += sl * xb.w;
                }
            }
        }

        // flush partials
#pragma unroll
        for (int l = 0; l < LN; ++l) {
#pragma unroll
            for (int k = 0; k < 4; ++k)
                atomicAdd(&g_U[l * CN + 4 * t + k], acc[l][k]);
#pragma unroll
            for (int k = 0; k < 4; ++k)
                atomicAdd(&g_U[l * CN + 1024 + 4 * t + k], acc[l][k + 4]);
        }
        if (t < LN) {
            atomicAdd(&g_denom[t], sden[t]);
            atomicAdd(&g_cnt[t],   scnt[t]);
        }

        // ---- last-block tail (threadFenceReduction pattern) ----
        __threadfence();                 // my atomics visible device-wide
        __syncthreads();                 // whole block past its fences
        if (t == 0)
            sIsLast = (atomicAdd(&g_done, 1u) == NPASS - 1);
        __syncthreads();

        if (sIsLast) {
            __threadfence();             // acquire side
            float den[LN], cnt[LN];
#pragma unroll
            for (int l = 0; l < LN; ++l) {
                den[l] = __ldcg(&g_denom[l]);   // L2 loads (atomic-written data)
                cnt[l] = __ldcg(&g_cnt[l]);
            }
#pragma unroll 4
            for (int idx = t; idx < LN * CN; idx += 256) {
                const int l = idx >> 11;
                const float u = __ldcg(&g_U[idx]);
                const float v = (cnt[l] > 0.0f) ? (u / den[l]) : __ldg(&rmean[idx]);
                out[(size_t)BN * CN + idx] = v;
                g_U[idx] = 0.0f;                 // reset for next replay
            }
            if (t < LN) { g_denom[t] = 0.0f; g_cnt[t] = 0.0f; }
            __syncthreads();
            if (t == 0) g_done = 0u;             // reset ticket
        }
    } else {
        // ================= ADJ (frozen R7 row body, strided rows) ==========
        const float DA = rsqrtf(4098.0f);   // rgb sample
        const float DB = rsqrtf(4100.0f);   // ir sample
        const float DC = rsqrtf(4097.0f);   // cam node

        for (int i = blockIdx.x - NPASS; i < MN; i += NADJ) {
            float lo, hi;                   // cols [0,4096) / [4096,8192)
            if (i < HALF)        { lo = DA * DA; hi = 0.0f;    }
            else if (i < BN)     { lo = 0.0f;    hi = DB * DB; }
            else if (i < BN + 4) { lo = 0.0f;    hi = DC * DB; }
            else                 { lo = DC * DA; hi = 0.0f;    }

            float2* row = (float2*)(out + ADJ_OFF + (size_t)i * MN);
            const float2 lo2 = make_float2(lo, lo);
            const float2 hi2 = make_float2(hi, hi);

#pragma unroll
            for (int k = 0; k < 8; ++k) __stcs(&row[t + 256 * k], lo2);
#pragma unroll
            for (int k = 0; k < 8; ++k) __stcs(&row[2048 + t + 256 * k], hi2);

            if (t < 3) {
                float2 tp = make_float2(0.0f, 0.0f);
                if (i < HALF) {
                    if (t == 2) tp = make_float2(DA * DC, DA * DC);
                } else if (i < BN) {
                    if (t < 2) tp = make_float2(DB * DC, DB * DC);
                } else {
                    const int l = i - BN;
                    if ((l >> 1) == t) {
                        if (l & 1) tp.y = DC * DC; else tp.x = DC * DC;
                    }
                }
                __stcs(&row[4096 + t], tp);
            }
        }
    }
}

// ---------------------------------------------------------------------------
extern "C" void kernel_launch(void* const* d_in, const int* in_sizes, int n_in,
                              void* d_out, int out_size)
{
    const float* x = nullptr; const int* cams = nullptr;
    const float* att_w = nullptr; const float* att_b = nullptr;
    const float* rmean = nullptr;

    for (int i = 0; i < n_in; ++i) {
        const int sz = in_sizes[i];
        if      (sz == BN * CN)           x = (const float*)d_in[i];
        else if (sz == BN)                cams = (const int*)d_in[i];
        else if (sz == LN * CN) { if (!att_w) att_w = (const float*)d_in[i];
                                  else        rmean = (const float*)d_in[i]; }
        else if (sz == LN)                att_b = (const float*)d_in[i];
    }

    fused_kernel<<<NBLKS, 256>>>(x, cams, att_w, att_b, rmean, (float*)d_out);
}

// round 12
// speedup vs baseline: 1.1629x; 1.1629x over previous
#include <cuda_runtime.h>
#include <cuda_bf16.h>
#include <math.h>

// Problem constants (fixed by the reference)
#define BN    8192
#define CN    2048
#define LN    6
#define HALF  4096
#define MN    (BN + LN)          // 8198
#define XOUT_ELEMS ((size_t)MN * CN)
#define ADJ_OFF    XOUT_ELEMS

#define G     4                  // rows staged per group
#define NGRP  16                 // groups per block (64 rows/block, grid 128)

// ---- scratch (no allocations allowed) ----
__device__ float g_U[LN * CN];   // sum_n s_n * x_n per cam
__device__ float g_denom[LN];    // per-cam sum of scores
__device__ float g_cnt[LN];      // per-cam counts

// ---------------------------------------------------------------------------
// 0) zero the scratch accumulators (graph replays reuse them)
// ---------------------------------------------------------------------------
__global__ void zero_kernel() {
    int idx = blockIdx.x * blockDim.x + threadIdx.x;
    if (idx < LN * CN) g_U[idx] = 0.0f;
    if (idx < LN) { g_denom[idx] = 0.0f; g_cnt[idx] = 0.0f; }
}

// ---------------------------------------------------------------------------
// 1) pass: R8 group-staged structure widened to 512 threads/block.
//    Rationale: R8's 140 regs x 256 thr pinned residency at 8 warps/SM
//    (register file, not smem). At 512 thr each thread owns 4 cols
//    (acc[6][4]) and prefetches 4 float4 -> ~90 regs, one block = 16
//    resident warps/SM: double the latency hiding for the same traffic.
//    64 rows/block in 16 groups of 4; 3 syncs/group as validated.
// ---------------------------------------------------------------------------
__global__ void __launch_bounds__(512) pass_kernel(
    const float* __restrict__ x, const int* __restrict__ cams,
    const float* __restrict__ att_w, const float* __restrict__ att_b,
    float* __restrict__ out)
{
    __shared__ float sx[G][CN];      // 32 KB staged rows
    __shared__ float sscore[G];
    __shared__ int   scam[G];
    __shared__ float sden[LN];
    __shared__ float scnt[LN];

    const int t = threadIdx.x;
    const int w = t >> 5, lane = t & 31;
    if (t < LN) { sden[t] = 0.0f; scnt[t] = 0.0f; }

    float acc[LN][4];
#pragma unroll
    for (int l = 0; l < LN; ++l)
#pragma unroll
        for (int k = 0; k < 4; ++k) acc[l][k] = 0.0f;

    const int r0 = blockIdx.x * (G * NGRP);          // 64 rows per block
    const float4* __restrict__ x4 = (const float4*)x;
    const float4* __restrict__ w4 = (const float4*)att_w;
    float4* __restrict__ o4 = (float4*)out;

    // preload group 0 (4 float4 per thread; row = f>>9, col4 = f&511)
    float4 buf[4];
#pragma unroll
    for (int m = 0; m < 4; ++m) {
        const int f = t + 512 * m;
        buf[m] = x4[(size_t)(r0 + (f >> 9)) * 512 + (f & 511)];
    }

    for (int g = 0; g < NGRP; ++g) {
        const int rows = r0 + G * g;

        __syncthreads();   // smem free (prev accumulate done; sden init on g=0)

        // stage to smem + fused copy to out
#pragma unroll
        for (int m = 0; m < 4; ++m) {
            const int f = t + 512 * m;
            const int rig = f >> 9, c4 = f & 511;
            *(float4*)&sx[rig][4 * c4] = buf[m];
            o4[(size_t)(rows + rig) * 512 + c4] = buf[m];
        }
        if (t < G) scam[t] = __ldg(&cams[rows + t]);
        __syncthreads();

        // score: warp w scores row w (w < G); pure warp ops, no block sync
        if (w < G) {
            const int cam = scam[w];
            float s = 0.0f;
#pragma unroll
            for (int k = 0; k < 16; ++k) {
                const int c4 = lane + 32 * k;
                const float4 xv = *(const float4*)&sx[w][4 * c4];
                const float4 wv = __ldg(&w4[(size_t)cam * 512 + c4]);
                s += xv.x * wv.x + xv.y * wv.y + xv.z * wv.z + xv.w * wv.w;
            }
#pragma unroll
            for (int o = 16; o > 0; o >>= 1) s += __shfl_down_sync(0xffffffffu, s, o);
            if (lane == 0) {
                s += __ldg(&att_b[cam]);
                sscore[w] = s;
                atomicAdd(&sden[cam], s);
                atomicAdd(&scnt[cam], 1.0f);
            }
        }
        __syncthreads();

        // issue next group's global loads BEFORE the accumulate (overlap)
        if (g + 1 < NGRP) {
#pragma unroll
            for (int m = 0; m < 4; ++m) {
                const int f = t + 512 * m;
                buf[m] = x4[(size_t)(rows + G + (f >> 9)) * 512 + (f & 511)];
            }
        }

        // accumulate: 4 rows x 4 owned cols (one conflict-free LDS.128/row)
#pragma unroll
        for (int r = 0; r < G; ++r) {
            const float s = sscore[r];
            const int cam = scam[r];
            const float4 xa = *(const float4*)&sx[r][4 * t];
#pragma unroll
            for (int l = 0; l < LN; ++l) {
                const float sl = (cam == l) ? s : 0.0f;
                acc[l][0] += sl * xa.x;  acc[l][1] += sl * xa.y;
                acc[l][2] += sl * xa.z;  acc[l][3] += sl * xa.w;
            }
        }
    }

    // flush partials (4 owned columns per thread)
#pragma unroll
    for (int l = 0; l < LN; ++l)
#pragma unroll
        for (int k = 0; k < 4; ++k)
            atomicAdd(&g_U[l * CN + 4 * t + k], acc[l][k]);
    if (t < LN) {
        atomicAdd(&g_denom[t], sden[t]);
        atomicAdd(&g_cnt[t],   scnt[t]);
    }
}

// ---------------------------------------------------------------------------
// 2) tail rows of x_out:  U/denom if cam present, else running_mean
// ---------------------------------------------------------------------------
__global__ void tail_kernel(const float* __restrict__ rmean,
                            float* __restrict__ out)
{
    int idx = blockIdx.x * blockDim.x + threadIdx.x;
    if (idx < LN * CN) {
        int l = idx >> 11;
        float v = (g_cnt[l] > 0.0f) ? (g_U[idx] / g_denom[l]) : __ldg(&rmean[idx]);
        out[(size_t)BN * CN + idx] = v;
    }
}

// ---------------------------------------------------------------------------
// 3) adj fill (FROZEN — ~41us @ 63% DRAM standalone): pure constant
//    segmented fill; rowsums pinned by the fixed batch layout.
// ---------------------------------------------------------------------------
__global__ void __launch_bounds__(256) adj_kernel(float* __restrict__ out)
{
    const int i = blockIdx.x;
    const int t = threadIdx.x;

    const float DA = rsqrtf(4098.0f);   // rgb sample
    const float DB = rsqrtf(4100.0f);   // ir sample
    const float DC = rsqrtf(4097.0f);   // cam node

    float lo, hi;                       // cols [0,4096) / [4096,8192)
    if (i < HALF)        { lo = DA * DA; hi = 0.0f;    }  // rgb sample row
    else if (i < BN)     { lo = 0.0f;    hi = DB * DB; }  // ir sample row
    else if (i < BN + 4) { lo = 0.0f;    hi = DC * DB; }  // rgb cam row
    else                 { lo = DC * DA; hi = 0.0f;    }  // ir cam row

    float2* row = (float2*)(out + ADJ_OFF + (size_t)i * MN);
    const float2 lo2 = make_float2(lo, lo);
    const float2 hi2 = make_float2(hi, hi);

#pragma unroll
    for (int k = 0; k < 8; ++k) __stcs(&row[t + 256 * k], lo2);          // cols 0..4095
#pragma unroll
    for (int k = 0; k < 8; ++k) __stcs(&row[2048 + t + 256 * k], hi2);   // cols 4096..8191

    // tail columns 8192..8197 (3 float2 pairs)
    if (t < 3) {
        float2 tp = make_float2(0.0f, 0.0f);
        if (i < HALF) {                        // rgb sample -> ir cams (8196,8197)
            if (t == 2) tp = make_float2(DA * DC, DA * DC);
        } else if (i < BN) {                   // ir sample -> rgb cams (8192..8195)
            if (t < 2) tp = make_float2(DB * DC, DB * DC);
        } else {                               // cam row: diagonal only
            const int l = i - BN;
            if ((l >> 1) == t) {
                if (l & 1) tp.y = DC * DC; else tp.x = DC * DC;
            }
        }
        __stcs(&row[4096 + t], tp);
    }
}

// ---------------------------------------------------------------------------
// Launch (FROZEN R10 structure — best validated): pass chain recorded first,
// adj on a least-priority stream rooted at the fork, joined at the end.
// ---------------------------------------------------------------------------
extern "C" void kernel_launch(void* const* d_in, const int* in_sizes, int n_in,
                              void* d_out, int out_size)
{
    const float* x = nullptr; const int* cams = nullptr;
    const float* att_w = nullptr; const float* att_b = nullptr;
    const float* rmean = nullptr;

    for (int i = 0; i < n_in; ++i) {
        const int sz = in_sizes[i];
        if      (sz == BN * CN)           x = (const float*)d_in[i];
        else if (sz == BN)                cams = (const int*)d_in[i];
        else if (sz == LN * CN) { if (!att_w) att_w = (const float*)d_in[i];
                                  else        rmean = (const float*)d_in[i]; }
        else if (sz == LN)                att_b = (const float*)d_in[i];
    }

    float* out = (float*)d_out;

    static cudaStream_t s2 = nullptr;
    static cudaEvent_t evFork = nullptr, evJoin = nullptr;
    if (s2 == nullptr) {
        int loPri = 0, hiPri = 0;
        cudaDeviceGetStreamPriorityRange(&loPri, &hiPri);
        cudaStreamCreateWithPriority(&s2, cudaStreamNonBlocking, loPri);
        cudaEventCreateWithFlags(&evFork, cudaEventDisableTiming);
        cudaEventCreateWithFlags(&evJoin, cudaEventDisableTiming);
    }

    cudaEventRecord(evFork, 0);

    zero_kernel<<<48, 256>>>();
    pass_kernel<<<128, 512>>>(x, cams, att_w, att_b, out);
    tail_kernel<<<48, 256>>>(rmean, out);

    cudaStreamWaitEvent(s2, evFork, 0);
    adj_kernel<<<MN, 256, 0, s2>>>(out);
    cudaEventRecord(evJoin, s2);

    cudaStreamWaitEvent(0, evJoin, 0);
}